// round 14
// baseline (speedup 1.0000x reference)
#include <cuda_runtime.h>
#include <math.h>

#define BB 16
#define DD 768
#define LL 96
#define CHUNK 128
#define NCHUNK 6
#define XPITCH 132   // 128 + 4 pad (bank-conflict-free staging)
#define SOFT_ELEMS (BB*LL*LL*DD)        // 113246208
#define HW_ELEMS   (BB*LL*LL*3)         // 442368
#define NINVALID (LL*(LL-1)/2)          // 4560
#define SPAN_SMEM_FLOATS (LL*XPITCH + LL + 192)

__constant__ float c_posw[6] = {2.0f, 1.5f, 1.0f, 0.8f, 0.3f, 0.5f};
__constant__ float c_depw[6] = {2.0f, 1.5f, 1.5f, 1.2f, 1.0f, 0.5f};

__device__ float g_E[BB*LL];     // exp(base/TEMP) per token
__device__ float g_base[BB*LL];  // raw base score bits (XLA mul/add path)
__device__ float g_S[BB*DD];     // per-(b,d) column sum of embeds

__device__ __forceinline__ int chain_len(int c2) {
    int m = min(c2, 190 - c2);
    return (m >> 1) + 1;
}

// ---------------------------------------------------------------------------
// prep (fast, ~3us): warp-per-d column sums; block x==0 also degree/E/base
// grid (96, 16), block 256
// ---------------------------------------------------------------------------
__global__ void prep_kernel(const float* __restrict__ x, const int* __restrict__ par,
                            const int* __restrict__ pos, const int* __restrict__ dep) {
    int b = blockIdx.y;
    int tid = threadIdx.x;
    int w = tid >> 5, lane = tid & 31;
    int d = blockIdx.x * 8 + w;

    const float* p = x + ((size_t)b*DD + d)*LL;
    float s = p[lane] + p[lane + 32] + p[lane + 64];
#pragma unroll
    for (int off = 16; off; off >>= 1) s += __shfl_down_sync(0xffffffffu, s, off);
    if (lane == 0) g_S[b*DD + d] = s;

    if (blockIdx.x == 0) {
        __shared__ int cnt[LL];
        if (tid < LL) cnt[tid] = 0;
        __syncthreads();
        if (tid < LL) atomicAdd(&cnt[par[b*LL + tid]], 1);
        __syncthreads();
        if (tid < LL) {
            // XLA elementwise, no fma contraction
            float t0 = __fmul_rn(1.5f, (float)cnt[tid]);
            float t1 = __fadd_rn(2.0f, t0);
            float t2 = __fadd_rn(t1, __fmul_rn(0.8f, c_posw[pos[b*LL + tid]]));
            float base = __fadd_rn(t2, __fmul_rn(0.5f, c_depw[dep[b*LL + tid]]));
            g_base[b*LL + tid] = base;
            g_E[b*LL + tid] = expf(base / 0.7f);
        }
    }
}

// ---------------------------------------------------------------------------
// lean per-warp center-chain walker (soft_heads only)
// ---------------------------------------------------------------------------
__device__ __forceinline__ void run_chain(
    const float* __restrict__ x_sm, const float* __restrict__ E_sm,
    const float* __restrict__ M2, const float4 Sa,
    float* __restrict__ out, int b, int c2, int chunk, int lane)
{
    const int dlo = (lane << 2);
    int l = c2 >> 1;
    int r = c2 - l;
    int kl = c2 - 2*l;   // 0 or 1
    int kr = 2*r - c2;   // 0 or 1

    const float* xl = x_sm + l*XPITCH + dlo;
    const float* xr = x_sm + r*XPITCH + dlo;

    float4 A = make_float4(0.f,0.f,0.f,0.f);
    float za = 0.f;

    auto addtok = [&](int t, int k, const float* xrow) {
        float a = E_sm[t] * M2[k] - 1.0f;
        za += a;
        float4 xa = *(const float4*)xrow;
        A.x += a*xa.x; A.y += a*xa.y; A.z += a*xa.z; A.w += a*xa.w;
    };

    addtok(l, kl, xl);
    if (r != l) addtok(r, kr, xr);

    float* o = out + ((size_t)((b*LL + l)*LL + r))*DD + chunk*CHUNK + dlo;
    const ptrdiff_t ODELTA = -(ptrdiff_t)(LL-1)*DD;

    while (1) {
        float invZ = __fdividef(1.0f, (float)LL + za);
        float4 o0;
        o0.x = (A.x + Sa.x)*invZ; o0.y = (A.y + Sa.y)*invZ;
        o0.z = (A.z + Sa.z)*invZ; o0.w = (A.w + Sa.w)*invZ;
        __stcs((float4*)o, o0);

        if (l == 0 || r == LL-1) break;
        --l; ++r; kl += 2; kr += 2;
        xl -= XPITCH; xr += XPITCH;
        addtok(l, kl, xl);
        addtok(r, kr, xr);
        o += ODELTA;
    }
}

// ---------------------------------------------------------------------------
// aux chain walker: incremental top-3 + Z; lane 0 emits hw/hi per span
// ---------------------------------------------------------------------------
__device__ void run_aux_chain(
    const float* __restrict__ sE, const float* __restrict__ sB,
    const float* __restrict__ sM2, const float* __restrict__ sMm,
    float* __restrict__ out, int b, int c2, int lane)
{
    int l = c2 >> 1;
    int r = c2 - l;
    int kl = c2 - 2*l;
    int kr = 2*r - c2;

    float za = 0.f;
    float y0 = -1e30f, y1 = -1e30f, y2 = -1e30f;
    int   i0 = 0x7fffffff, i1 = 0x7fffffff, i2 = 0x7fffffff;

    auto addtok = [&](int t, int k) {
        za += sE[t] * sM2[k] - 1.0f;
        float y = __fadd_rn(sB[t], sMm[k]);   // JAX score bits (order key)
        bool q0 = (y > y0) || (y == y0 && t < i0);
        bool q1 = (y > y1) || (y == y1 && t < i1);
        bool q2 = (y > y2) || (y == y2 && t < i2);
        if (q0)      { y2=y1; i2=i1; y1=y0; i1=i0; y0=y; i0=t; }
        else if (q1) { y2=y1; i2=i1; y1=y; i1=t; }
        else if (q2) { y2=y;  i2=t; }
    };

    addtok(l, kl);
    if (r != l) addtok(r, kr);

    float* hw = out + SOFT_ELEMS + (size_t)((b*LL + l)*LL + r)*3;
    float* hi = hw + HW_ELEMS;
    const ptrdiff_t HDELTA = -(ptrdiff_t)(LL-1)*3;

    while (1) {
        if (lane == 0) {
            float invZ = __fdividef(1.0f, (float)LL + za);
            int len = r - l + 1;
            int k0 = 2*i0 - c2; k0 = k0 < 0 ? -k0 : k0;
            float w0 = sE[i0] * sM2[k0];
            float hv1, hv2, fi1, fi2;
            if (len >= 3) {
                int k1 = 2*i1 - c2; k1 = k1 < 0 ? -k1 : k1;
                int k2v = 2*i2 - c2; k2v = k2v < 0 ? -k2v : k2v;
                hv1 = sE[i1]*sM2[k1]*invZ;  fi1 = (float)i1;
                hv2 = sE[i2]*sM2[k2v]*invZ; fi2 = (float)i2;
            } else if (len == 2) {
                int k1 = 2*i1 - c2; k1 = k1 < 0 ? -k1 : k1;
                hv1 = sE[i1]*sM2[k1]*invZ;  fi1 = (float)i1;
                hv2 = invZ;                 fi2 = (l > 0) ? 0.f : (float)(r+1);
            } else {
                hv1 = invZ; hv2 = invZ;
                if (l == 0)      { fi1 = 1.f; fi2 = 2.f; }
                else if (l == 1) { fi1 = 0.f; fi2 = 2.f; }
                else             { fi1 = 0.f; fi2 = 1.f; }
            }
            hw[0] = w0*invZ; hw[1] = hv1; hw[2] = hv2;
            hi[0] = (float)i0; hi[1] = fi1; hi[2] = fi2;
        }
        if (l == 0 || r == LL-1) break;
        --l; ++r; kl += 2; kr += 2;
        addtok(l, kl);
        addtok(r, kr);
        hw += HDELTA; hi += HDELTA;
    }
}

// ---------------------------------------------------------------------------
// span kernel: grid (37, 16), block 384, 4 CTA/SM -> 592 CTAs = EXACTLY 1 wave
//   lin < 36 : span CTA; chunk = lin/6, g = lin%6; warp v = g*12+wid in [0,72)
//              chains {v, v+72, v+144<=190} + anti-balanced zero rows
//              (every warp stores exactly 128 rows x 512 B)
//   lin == 36: aux CTA (one per b) — warp w walks chains c2 = w + 12k
//              incrementally, lane0 emits hw/hi; fills invalid hw/hi rows.
//              Runs concurrently with span CTAs (hidden under store wall).
// ---------------------------------------------------------------------------
__global__ void __launch_bounds__(384, 4)
span_kernel(const float* __restrict__ x, float* __restrict__ out, int write_aux) {
    int lin = blockIdx.x, b = blockIdx.y;
    int tid = threadIdx.x;
    extern __shared__ float sm[];

    if (lin == 36) {
        // ---------------- aux CTA ----------------
        if (!write_aux) return;
        float* sE  = sm;            // [96]
        float* sB  = sm + LL;       // [96]
        float* sM2 = sm + 2*LL;     // [192]
        float* sMm = sM2 + 192;     // [192]
        for (int k = tid; k < 191; k += 384) {
            float denom = __fadd_rn(1.0f, 0.5f*(float)k);   // exact
            float med = __fdiv_rn(0.5f, denom);             // JAX medoid bits
            sMm[k] = med;
            sM2[k] = expf(med / 0.7f);
        }
        if (tid < LL) {
            sE[tid] = g_E[b*LL + tid];
            sB[tid] = g_base[b*LL + tid];
        }
        __syncthreads();

        int w = tid >> 5, lane = tid & 31;
#pragma unroll 1
        for (int k = 0; k < 16; ++k) {
            int c2 = w + 12*k;
            if (c2 <= 190)
                run_aux_chain(sE, sB, sM2, sMm, out, b, c2, lane);
        }

        // invalid aux rows: hw = 0, hi = -1
        float* hw_base = out + SOFT_ELEMS;
        float* hi_base = hw_base + HW_ELEMS;
        for (int j = tid; j < NINVALID; j += 384) {
            int l = (int)((1.0f + sqrtf(8.0f*(float)j + 1.0f)) * 0.5f);
            while (l*(l-1)/2 > j) --l;
            while (l*(l+1)/2 <= j) ++l;
            int r = j - l*(l-1)/2;
            size_t row = (size_t)(b*LL + l)*LL + r;
            float* hw = hw_base + row*3;
            float* hi = hi_base + row*3;
            hw[0] = 0.f; hw[1] = 0.f; hw[2] = 0.f;
            hi[0] = -1.f; hi[1] = -1.f; hi[2] = -1.f;
        }
        return;
    }

    // ---------------- span CTA ----------------
    int chunk = lin / 6, g = lin - chunk*6;

    float* x_sm = sm;                 // [96][132]
    float* E_sm = sm + LL*XPITCH;     // [96]
    float* M2   = E_sm + LL;          // [192]

    const float* gx = x + ((size_t)b*DD + (size_t)chunk*CHUNK)*LL;
    for (int i = tid; i < CHUNK*LL; i += 384) {
        int d = i / LL;
        int t = i - d*LL;
        x_sm[t*XPITCH + d] = gx[i];
    }
    for (int k = tid; k < 191; k += 384) {
        float denom = __fadd_rn(1.0f, 0.5f*(float)k);
        M2[k] = expf(__fdiv_rn(0.5f, denom) / 0.7f);
    }
    if (tid < LL) E_sm[tid] = g_E[b*LL + tid];
    __syncthreads();

    int wid = tid >> 5, lane = tid & 31;
    int v = g*12 + wid;                     // [0,72)

    const int dlo = (lane << 2);
    const float* Sp = g_S + b*DD + chunk*CHUNK + dlo;
    float4 Sa = *(const float4*)Sp;

    run_chain(x_sm, E_sm, M2, Sa, out, b, v,      chunk, lane);
    run_chain(x_sm, E_sm, M2, Sa, out, b, v + 72, chunk, lane);
    if (v + 144 <= 190)
        run_chain(x_sm, E_sm, M2, Sa, out, b, v + 144, chunk, lane);

    // ---- zero duty: contiguous block of invalid rows, anti-balanced ----
    int load_v = chain_len(v) + chain_len(v + 72)
               + ((v + 144 <= 190) ? chain_len(v + 144) : 0);
    int start = 0;
    for (int v2 = 0; v2 < v; ++v2) {
        int lv = chain_len(v2) + chain_len(v2 + 72)
               + ((v2 + 144 <= 190) ? chain_len(v2 + 144) : 0);
        start += 128 - lv;
    }
    int rows = 128 - load_v;

    int j = start;
    int l = (int)((1.0f + sqrtf(8.0f*(float)j + 1.0f)) * 0.5f);
    while (l*(l-1)/2 > j) --l;
    while (l*(l+1)/2 <= j) ++l;
    int r = j - l*(l-1)/2;

    float4 zz = make_float4(0.f, 0.f, 0.f, 0.f);
    float* zp = out + ((size_t)(b*LL + l)*LL + r)*DD + chunk*CHUNK + dlo;
    for (int n = 0; n < rows; ++n) {
        __stcs((float4*)zp, zz);
        ++r; zp += DD;
        if (r == l) {
            ++l; r = 0;
            zp = out + ((size_t)(b*LL + l)*LL)*DD + chunk*CHUNK + dlo;
        }
    }
}

// ---------------------------------------------------------------------------
extern "C" void kernel_launch(void* const* d_in, const int* in_sizes, int n_in,
                              void* d_out, int out_size) {
    const float* x  = (const float*)d_in[0];
    const int* par  = (const int*)d_in[1];
    const int* pos  = (const int*)d_in[2];
    const int* dep  = (const int*)d_in[3];
    float* out = (float*)d_out;

    int write_aux = (out_size >= SOFT_ELEMS + 2*HW_ELEMS) ? 1 : 0;

    prep_kernel<<<dim3(96, BB), 256>>>(x, par, pos, dep);

    int smem = SPAN_SMEM_FLOATS * 4;
    cudaFuncSetAttribute(span_kernel, cudaFuncAttributeMaxDynamicSharedMemorySize, smem);
    span_kernel<<<dim3(37, BB), 384, smem>>>(x, out, write_aux);
}

// round 15
// speedup vs baseline: 4.0376x; 4.0376x over previous
#include <cuda_runtime.h>
#include <math.h>

#define BB 16
#define DD 768
#define LL 96
#define CHUNK 128
#define NCHUNK 6
#define XPITCH 132   // 128 + 4 pad (bank-conflict-free staging)
#define SOFT_ELEMS (BB*LL*LL*DD)        // 113246208
#define HW_ELEMS   (BB*LL*LL*3)         // 442368
#define SPAN_SMEM_FLOATS (LL*XPITCH + 2*LL + 2*192)

__constant__ float c_posw[6] = {2.0f, 1.5f, 1.0f, 0.8f, 0.3f, 0.5f};
__constant__ float c_depw[6] = {2.0f, 1.5f, 1.5f, 1.2f, 1.0f, 0.5f};

__device__ float g_E[BB*LL];     // exp(base/TEMP) per token
__device__ float g_base[BB*LL];  // raw base score bits (XLA mul/add path)
__device__ float g_S[BB*DD];     // per-(b,d) column sum of embeds

__device__ __forceinline__ int chain_len(int c2) {
    int m = min(c2, 190 - c2);
    return (m >> 1) + 1;
}

// ---------------------------------------------------------------------------
// prep (fast, ~3us): warp-per-d column sums; block x==0 also degree/E/base
// grid (96, 16), block 256
// ---------------------------------------------------------------------------
__global__ void prep_kernel(const float* __restrict__ x, const int* __restrict__ par,
                            const int* __restrict__ pos, const int* __restrict__ dep) {
    int b = blockIdx.y;
    int tid = threadIdx.x;
    int w = tid >> 5, lane = tid & 31;
    int d = blockIdx.x * 8 + w;

    const float* p = x + ((size_t)b*DD + d)*LL;
    float s = p[lane] + p[lane + 32] + p[lane + 64];
#pragma unroll
    for (int off = 16; off; off >>= 1) s += __shfl_down_sync(0xffffffffu, s, off);
    if (lane == 0) g_S[b*DD + d] = s;

    if (blockIdx.x == 0) {
        __shared__ int cnt[LL];
        if (tid < LL) cnt[tid] = 0;
        __syncthreads();
        if (tid < LL) atomicAdd(&cnt[par[b*LL + tid]], 1);
        __syncthreads();
        if (tid < LL) {
            // XLA elementwise, no fma contraction
            float t0 = __fmul_rn(1.5f, (float)cnt[tid]);
            float t1 = __fadd_rn(2.0f, t0);
            float t2 = __fadd_rn(t1, __fmul_rn(0.8f, c_posw[pos[b*LL + tid]]));
            float base = __fadd_rn(t2, __fmul_rn(0.5f, c_depw[dep[b*LL + tid]]));
            g_base[b*LL + tid] = base;
            g_E[b*LL + tid] = expf(base / 0.7f);
        }
    }
}

// ---------------------------------------------------------------------------
// per-warp center-chain walker; AUX adds incremental top-3 + lane0 hw/hi emit
// ---------------------------------------------------------------------------
template<bool AUX>
__device__ __forceinline__ void run_chain(
    const float* __restrict__ x_sm, const float* __restrict__ E_sm,
    const float* __restrict__ B_sm, const float* __restrict__ M2,
    const float* __restrict__ Mm, const float4 Sa,
    float* __restrict__ out, int b, int c2, int chunk, int lane)
{
    const int dlo = (lane << 2);
    int l = c2 >> 1;
    int r = c2 - l;
    int kl = c2 - 2*l;   // 0 or 1
    int kr = 2*r - c2;   // 0 or 1

    const float* xl = x_sm + l*XPITCH + dlo;
    const float* xr = x_sm + r*XPITCH + dlo;

    float4 A = make_float4(0.f,0.f,0.f,0.f);
    float za = 0.f;
    float y0 = -1e30f, y1 = -1e30f, y2 = -1e30f;
    int   i0 = 0x7fffffff, i1 = 0x7fffffff, i2 = 0x7fffffff;

    auto addtok = [&](int t, int k, const float* xrow) {
        float a = E_sm[t] * M2[k] - 1.0f;
        if constexpr (AUX) {
            float y = __fadd_rn(B_sm[t], Mm[k]);   // JAX score bits (order key)
            bool q0 = (y > y0) || (y == y0 && t < i0);
            bool q1 = (y > y1) || (y == y1 && t < i1);
            bool q2 = (y > y2) || (y == y2 && t < i2);
            if (q0)      { y2=y1; i2=i1; y1=y0; i1=i0; y0=y; i0=t; }
            else if (q1) { y2=y1; i2=i1; y1=y; i1=t; }
            else if (q2) { y2=y;  i2=t; }
        }
        za += a;
        float4 xa = *(const float4*)xrow;
        A.x += a*xa.x; A.y += a*xa.y; A.z += a*xa.z; A.w += a*xa.w;
    };

    addtok(l, kl, xl);
    if (r != l) addtok(r, kr, xr);

    float* o = out + ((size_t)((b*LL + l)*LL + r))*DD + chunk*CHUNK + dlo;
    float* hw = out + SOFT_ELEMS + (size_t)((b*LL + l)*LL + r)*3;
    const ptrdiff_t ODELTA = -(ptrdiff_t)(LL-1)*DD;
    const ptrdiff_t HDELTA = -(ptrdiff_t)(LL-1)*3;

    while (1) {
        float invZ = __fdividef(1.0f, (float)LL + za);
        float4 o0;
        o0.x = (A.x + Sa.x)*invZ; o0.y = (A.y + Sa.y)*invZ;
        o0.z = (A.z + Sa.z)*invZ; o0.w = (A.w + Sa.w)*invZ;
        __stcs((float4*)o, o0);

        if constexpr (AUX) {
            if (lane == 0) {
                int len = r - l + 1;
                int k0 = 2*i0 - c2; k0 = k0 < 0 ? -k0 : k0;
                float w0 = E_sm[i0] * M2[k0];
                float hv1, hv2, fi1, fi2;
                if (len >= 3) {
                    int k1 = 2*i1 - c2; k1 = k1 < 0 ? -k1 : k1;
                    int k2v = 2*i2 - c2; k2v = k2v < 0 ? -k2v : k2v;
                    hv1 = E_sm[i1]*M2[k1]*invZ;  fi1 = (float)i1;
                    hv2 = E_sm[i2]*M2[k2v]*invZ; fi2 = (float)i2;
                } else if (len == 2) {
                    int k1 = 2*i1 - c2; k1 = k1 < 0 ? -k1 : k1;
                    hv1 = E_sm[i1]*M2[k1]*invZ;  fi1 = (float)i1;
                    hv2 = invZ;                  fi2 = (l > 0) ? 0.f : (float)(r+1);
                } else {
                    hv1 = invZ; hv2 = invZ;
                    if (l == 0)      { fi1 = 1.f; fi2 = 2.f; }
                    else if (l == 1) { fi1 = 0.f; fi2 = 2.f; }
                    else             { fi1 = 0.f; fi2 = 1.f; }
                }
                hw[0] = w0*invZ; hw[1] = hv1; hw[2] = hv2;
                hw[HW_ELEMS+0] = (float)i0; hw[HW_ELEMS+1] = fi1; hw[HW_ELEMS+2] = fi2;
            }
        }

        if (l == 0 || r == LL-1) break;
        --l; ++r; kl += 2; kr += 2;
        xl -= XPITCH; xr += XPITCH;
        addtok(l, kl, xl);
        addtok(r, kr, xr);
        o += ODELTA;
        if constexpr (AUX) hw += HDELTA;
    }
}

// ---------------------------------------------------------------------------
// span kernel: grid (6, 6, 16) = 576 CTAs, block 384, 4 CTA/SM -> ONE WAVE.
// Warp v = g*12+wid in [0,72): chains {v, v+72, v+144<=190}; a chain carries
// AUX (top-3 emit) only in the chunk where c2 % 6 == chunk (even spread).
// Then anti-balanced zero rows (every warp stores exactly 128 rows x 512 B);
// chunk-0 zero duty also writes invalid hw=0 / hi=-1.
// ---------------------------------------------------------------------------
__global__ void __launch_bounds__(384, 4)
span_kernel(const float* __restrict__ x, float* __restrict__ out, int write_aux) {
    int g = blockIdx.x, chunk = blockIdx.y, b = blockIdx.z;
    int tid = threadIdx.x;

    extern __shared__ float sm[];
    float* x_sm = sm;                 // [96][132]
    float* E_sm = sm + LL*XPITCH;     // [96]
    float* B_sm = E_sm + LL;          // [96]
    float* M2   = B_sm + LL;          // [192]
    float* Mm   = M2 + 192;           // [192]

    const float* gx = x + ((size_t)b*DD + (size_t)chunk*CHUNK)*LL;
    for (int i = tid; i < CHUNK*LL; i += 384) {
        int d = i / LL;
        int t = i - d*LL;
        x_sm[t*XPITCH + d] = gx[i];
    }
    for (int k = tid; k < 191; k += 384) {
        float denom = __fadd_rn(1.0f, 0.5f*(float)k);   // exact
        float med = __fdiv_rn(0.5f, denom);             // JAX medoid bits
        Mm[k] = med;
        M2[k] = expf(med / 0.7f);
    }
    if (tid < LL) {
        E_sm[tid] = g_E[b*LL + tid];
        B_sm[tid] = g_base[b*LL + tid];
    }
    __syncthreads();

    int wid = tid >> 5, lane = tid & 31;
    int v = g*12 + wid;                     // [0,72)

    const int dlo = (lane << 2);
    const float* Sp = g_S + b*DD + chunk*CHUNK + dlo;
    float4 Sa = *(const float4*)Sp;

    auto do_chain = [&](int c2) {
        if (write_aux && (c2 % 6) == chunk)
            run_chain<true >(x_sm, E_sm, B_sm, M2, Mm, Sa, out, b, c2, chunk, lane);
        else
            run_chain<false>(x_sm, E_sm, B_sm, M2, Mm, Sa, out, b, c2, chunk, lane);
    };

    do_chain(v);
    do_chain(v + 72);
    if (v + 144 <= 190) do_chain(v + 144);

    // ---- zero duty: contiguous block of invalid rows, anti-balanced ----
    int load_v = chain_len(v) + chain_len(v + 72)
               + ((v + 144 <= 190) ? chain_len(v + 144) : 0);
    int start = 0;
    for (int v2 = 0; v2 < v; ++v2) {
        int lv = chain_len(v2) + chain_len(v2 + 72)
               + ((v2 + 144 <= 190) ? chain_len(v2 + 144) : 0);
        start += 128 - lv;
    }
    int rows = 128 - load_v;

    int j = start;
    int l = (int)((1.0f + sqrtf(8.0f*(float)j + 1.0f)) * 0.5f);
    while (l*(l-1)/2 > j) --l;
    while (l*(l+1)/2 <= j) ++l;
    int r = j - l*(l-1)/2;

    bool auxz = (chunk == 0) && write_aux;
    float4 zz = make_float4(0.f, 0.f, 0.f, 0.f);
    float* zp = out + ((size_t)(b*LL + l)*LL + r)*DD + chunk*CHUNK + dlo;
    float* hwp = out + SOFT_ELEMS + ((size_t)(b*LL + l)*LL + r)*3;
    for (int n = 0; n < rows; ++n) {
        __stcs((float4*)zp, zz);
        if (auxz) {
            if (lane < 3)      hwp[lane] = 0.f;
            else if (lane < 6) hwp[HW_ELEMS + lane - 3] = -1.f;
        }
        ++r; zp += DD; hwp += 3;
        if (r == l) {
            ++l; r = 0;
            zp  = out + ((size_t)(b*LL + l)*LL)*DD + chunk*CHUNK + dlo;
            hwp = out + SOFT_ELEMS + ((size_t)(b*LL + l)*LL)*3;
        }
    }
}

// ---------------------------------------------------------------------------
extern "C" void kernel_launch(void* const* d_in, const int* in_sizes, int n_in,
                              void* d_out, int out_size) {
    const float* x  = (const float*)d_in[0];
    const int* par  = (const int*)d_in[1];
    const int* pos  = (const int*)d_in[2];
    const int* dep  = (const int*)d_in[3];
    float* out = (float*)d_out;

    int write_aux = (out_size >= SOFT_ELEMS + 2*HW_ELEMS) ? 1 : 0;

    prep_kernel<<<dim3(96, BB), 256>>>(x, par, pos, dep);

    int smem = SPAN_SMEM_FLOATS * 4;
    cudaFuncSetAttribute(span_kernel, cudaFuncAttributeMaxDynamicSharedMemorySize, smem);
    span_kernel<<<dim3(6, NCHUNK, BB), 384, smem>>>(x, out, write_aux);
}

// round 16
// speedup vs baseline: 4.4282x; 1.0967x over previous
#include <cuda_runtime.h>
#include <math.h>

#define BB 16
#define DD 768
#define LL 96
#define CHUNK 128
#define NCHUNK 6
#define XPITCH 132   // 128 + 4 pad (bank-conflict-free staging)
#define SOFT_ELEMS (BB*LL*LL*DD)        // 113246208
#define HW_ELEMS   (BB*LL*LL*3)         // 442368
#define NINVALID (LL*(LL-1)/2)          // 4560
#define SPAN_SMEM_FLOATS (LL*XPITCH + 2*LL + 2*192)

__constant__ float c_posw[6] = {2.0f, 1.5f, 1.0f, 0.8f, 0.3f, 0.5f};
__constant__ float c_depw[6] = {2.0f, 1.5f, 1.5f, 1.2f, 1.0f, 0.5f};

__device__ float g_E[BB*LL];     // exp(base/TEMP) per token
__device__ float g_base[BB*LL];  // raw base score bits (XLA mul/add path)
__device__ float g_S[BB*DD];     // per-(b,d) column sum of embeds

__device__ __forceinline__ int chain_len(int c2) {
    int m = min(c2, 190 - c2);
    return (m >> 1) + 1;
}

// length of the aux chain warp v2 carries in this chunk (0 if none)
__device__ __forceinline__ int aux_len_for(int v2, int chunk) {
    int k = chunk - (v2 % 6);
    k = (k % 6 + 6) % 6;
    if (k > 2) return 0;
    int c2 = v2 + 72*k;
    if (c2 > 190) return 0;
    return chain_len(c2);
}

// ---------------------------------------------------------------------------
// prep (fast, ~3us): warp-per-d column sums; block x==0 also degree/E/base
// ---------------------------------------------------------------------------
__global__ void prep_kernel(const float* __restrict__ x, const int* __restrict__ par,
                            const int* __restrict__ pos, const int* __restrict__ dep) {
    int b = blockIdx.y;
    int tid = threadIdx.x;
    int w = tid >> 5, lane = tid & 31;
    int d = blockIdx.x * 8 + w;

    const float* p = x + ((size_t)b*DD + d)*LL;
    float s = p[lane] + p[lane + 32] + p[lane + 64];
#pragma unroll
    for (int off = 16; off; off >>= 1) s += __shfl_down_sync(0xffffffffu, s, off);
    if (lane == 0) g_S[b*DD + d] = s;

    if (blockIdx.x == 0) {
        __shared__ int cnt[LL];
        if (tid < LL) cnt[tid] = 0;
        __syncthreads();
        if (tid < LL) atomicAdd(&cnt[par[b*LL + tid]], 1);
        __syncthreads();
        if (tid < LL) {
            // XLA elementwise, no fma contraction
            float t0 = __fmul_rn(1.5f, (float)cnt[tid]);
            float t1 = __fadd_rn(2.0f, t0);
            float t2 = __fadd_rn(t1, __fmul_rn(0.8f, c_posw[pos[b*LL + tid]]));
            float base = __fadd_rn(t2, __fmul_rn(0.5f, c_depw[dep[b*LL + tid]]));
            g_base[b*LL + tid] = base;
            g_E[b*LL + tid] = expf(base / 0.7f);
        }
    }
}

// ---------------------------------------------------------------------------
// per-warp center-chain walker; AUX adds incremental top-3 + lane0 hw/hi emit
// ---------------------------------------------------------------------------
template<bool AUX>
__device__ __forceinline__ void run_chain(
    const float* __restrict__ x_sm, const float* __restrict__ E_sm,
    const float* __restrict__ B_sm, const float* __restrict__ M2,
    const float* __restrict__ Mm, const float4 Sa,
    float* __restrict__ out, int b, int c2, int chunk, int lane)
{
    const int dlo = (lane << 2);
    int l = c2 >> 1;
    int r = c2 - l;
    int kl = c2 - 2*l;   // 0 or 1
    int kr = 2*r - c2;   // 0 or 1

    const float* xl = x_sm + l*XPITCH + dlo;
    const float* xr = x_sm + r*XPITCH + dlo;

    float4 A = make_float4(0.f,0.f,0.f,0.f);
    float za = 0.f;
    float y0 = -1e30f, y1 = -1e30f, y2 = -1e30f;
    int   i0 = 0x7fffffff, i1 = 0x7fffffff, i2 = 0x7fffffff;

    auto addtok = [&](int t, int k, const float* xrow) {
        float a = E_sm[t] * M2[k] - 1.0f;
        if constexpr (AUX) {
            float y = __fadd_rn(B_sm[t], Mm[k]);   // JAX score bits (order key)
            bool q0 = (y > y0) || (y == y0 && t < i0);
            bool q1 = (y > y1) || (y == y1 && t < i1);
            bool q2 = (y > y2) || (y == y2 && t < i2);
            if (q0)      { y2=y1; i2=i1; y1=y0; i1=i0; y0=y; i0=t; }
            else if (q1) { y2=y1; i2=i1; y1=y; i1=t; }
            else if (q2) { y2=y;  i2=t; }
        }
        za += a;
        float4 xa = *(const float4*)xrow;
        A.x += a*xa.x; A.y += a*xa.y; A.z += a*xa.z; A.w += a*xa.w;
    };

    addtok(l, kl, xl);
    if (r != l) addtok(r, kr, xr);

    float* o = out + ((size_t)((b*LL + l)*LL + r))*DD + chunk*CHUNK + dlo;
    float* hw = out + SOFT_ELEMS + (size_t)((b*LL + l)*LL + r)*3;
    const ptrdiff_t ODELTA = -(ptrdiff_t)(LL-1)*DD;
    const ptrdiff_t HDELTA = -(ptrdiff_t)(LL-1)*3;

    while (1) {
        float invZ = __fdividef(1.0f, (float)LL + za);
        float4 o0;
        o0.x = (A.x + Sa.x)*invZ; o0.y = (A.y + Sa.y)*invZ;
        o0.z = (A.z + Sa.z)*invZ; o0.w = (A.w + Sa.w)*invZ;
        __stcs((float4*)o, o0);

        if constexpr (AUX) {
            if (lane == 0) {
                int len = r - l + 1;
                int k0 = 2*i0 - c2; k0 = k0 < 0 ? -k0 : k0;
                float w0 = E_sm[i0] * M2[k0];
                float hv1, hv2, fi1, fi2;
                if (len >= 3) {
                    int k1 = 2*i1 - c2; k1 = k1 < 0 ? -k1 : k1;
                    int k2v = 2*i2 - c2; k2v = k2v < 0 ? -k2v : k2v;
                    hv1 = E_sm[i1]*M2[k1]*invZ;  fi1 = (float)i1;
                    hv2 = E_sm[i2]*M2[k2v]*invZ; fi2 = (float)i2;
                } else if (len == 2) {
                    int k1 = 2*i1 - c2; k1 = k1 < 0 ? -k1 : k1;
                    hv1 = E_sm[i1]*M2[k1]*invZ;  fi1 = (float)i1;
                    hv2 = invZ;                  fi2 = (l > 0) ? 0.f : (float)(r+1);
                } else {
                    hv1 = invZ; hv2 = invZ;
                    if (l == 0)      { fi1 = 1.f; fi2 = 2.f; }
                    else if (l == 1) { fi1 = 0.f; fi2 = 2.f; }
                    else             { fi1 = 0.f; fi2 = 1.f; }
                }
                hw[0] = w0*invZ; hw[1] = hv1; hw[2] = hv2;
                hw[HW_ELEMS+0] = (float)i0; hw[HW_ELEMS+1] = fi1; hw[HW_ELEMS+2] = fi2;
            }
        }

        if (l == 0 || r == LL-1) break;
        --l; ++r; kl += 2; kr += 2;
        xl -= XPITCH; xr += XPITCH;
        addtok(l, kl, xl);
        addtok(r, kr, xr);
        o += ODELTA;
        if constexpr (AUX) hw += HDELTA;
    }
}

// ---------------------------------------------------------------------------
// span kernel: grid (6, 6, 16) = 576 CTAs, block 384, 4 CTA/SM -> ONE WAVE.
// Warp v: chains {v, v+72, v+144<=190}; chain k carries AUX iff (v+k)%6==chunk
// (each warp <= 1 aux chain per chunk). Zero rows allocated by exact weighted
// prefix (aux spans cost double) so warp finish times stay level; chunk-0 zero
// duty also writes invalid hw=0 / hi=-1.
// ---------------------------------------------------------------------------
__global__ void __launch_bounds__(384, 4)
span_kernel(const float* __restrict__ x, float* __restrict__ out, int write_aux) {
    int g = blockIdx.x, chunk = blockIdx.y, b = blockIdx.z;
    int tid = threadIdx.x;

    extern __shared__ float sm[];
    float* x_sm = sm;                 // [96][132]
    float* E_sm = sm + LL*XPITCH;     // [96]
    float* B_sm = E_sm + LL;          // [96]
    float* M2   = B_sm + LL;          // [192]
    float* Mm   = M2 + 192;           // [192]

    const float* gx = x + ((size_t)b*DD + (size_t)chunk*CHUNK)*LL;
    for (int i = tid; i < CHUNK*LL; i += 384) {
        int d = i / LL;
        int t = i - d*LL;
        x_sm[t*XPITCH + d] = gx[i];
    }
    for (int k = tid; k < 191; k += 384) {
        float denom = __fadd_rn(1.0f, 0.5f*(float)k);   // exact
        float med = __fdiv_rn(0.5f, denom);             // JAX medoid bits
        Mm[k] = med;
        M2[k] = expf(med / 0.7f);
    }
    if (tid < LL) {
        E_sm[tid] = g_E[b*LL + tid];
        B_sm[tid] = g_base[b*LL + tid];
    }
    __syncthreads();

    int wid = tid >> 5, lane = tid & 31;
    int v = g*12 + wid;                     // [0,72)

    const int dlo = (lane << 2);
    const float* Sp = g_S + b*DD + chunk*CHUNK + dlo;
    float4 Sa = *(const float4*)Sp;

    auto do_chain = [&](int c2, int k) {
        if (write_aux && ((v + k) % 6) == chunk)
            run_chain<true >(x_sm, E_sm, B_sm, M2, Mm, Sa, out, b, c2, chunk, lane);
        else
            run_chain<false>(x_sm, E_sm, B_sm, M2, Mm, Sa, out, b, c2, chunk, lane);
    };

    do_chain(v, 0);
    do_chain(v + 72, 1);
    if (v + 144 <= 190) do_chain(v + 144, 2);

    // ---- zero duty: exact weighted allocation of the 4560 invalid rows ----
    // half-unit costs: zero row = 2, span = 2, aux span = +2 extra
    int G = 0, Fprev = 0, hv = 0;
    for (int v2 = 0; v2 < 72; ++v2) {
        int load = chain_len(v2) + chain_len(v2 + 72)
                 + ((v2 + 144 <= 190) ? chain_len(v2 + 144) : 0);
        int h = 2*load + (write_aux ? 2*aux_len_for(v2, chunk) : 0);
        if (v2 < v) Fprev += h;
        if (v2 == v) hv = h;
        G += h;
    }
    G += 2*NINVALID;
    int Tprev = (v * G) / 72;
    int Tv    = ((v + 1) * G) / 72;
    int start = (Tprev - Fprev) >> 1;
    int rows  = ((Tv - Fprev - hv) >> 1) - start;

    int j = start;
    int l = (int)((1.0f + sqrtf(8.0f*(float)j + 1.0f)) * 0.5f);
    while (l*(l-1)/2 > j) --l;
    while (l*(l+1)/2 <= j) ++l;
    int r = j - l*(l-1)/2;

    bool auxz = (chunk == 0) && write_aux;
    float4 zz = make_float4(0.f, 0.f, 0.f, 0.f);
    float* zp  = out + ((size_t)(b*LL + l)*LL + r)*DD + chunk*CHUNK + dlo;
    float* hwp = out + SOFT_ELEMS + ((size_t)(b*LL + l)*LL + r)*3;
    for (int n = 0; n < rows; ++n) {
        __stcs((float4*)zp, zz);
        if (auxz) {
            if (lane < 3)      hwp[lane] = 0.f;
            else if (lane < 6) hwp[HW_ELEMS + lane - 3] = -1.f;
        }
        ++r; zp += DD; hwp += 3;
        if (r == l) {
            ++l; r = 0;
            zp  = out + ((size_t)(b*LL + l)*LL)*DD + chunk*CHUNK + dlo;
            hwp = out + SOFT_ELEMS + ((size_t)(b*LL + l)*LL)*3;
        }
    }
}

// ---------------------------------------------------------------------------
extern "C" void kernel_launch(void* const* d_in, const int* in_sizes, int n_in,
                              void* d_out, int out_size) {
    const float* x  = (const float*)d_in[0];
    const int* par  = (const int*)d_in[1];
    const int* pos  = (const int*)d_in[2];
    const int* dep  = (const int*)d_in[3];
    float* out = (float*)d_out;

    int write_aux = (out_size >= SOFT_ELEMS + 2*HW_ELEMS) ? 1 : 0;

    prep_kernel<<<dim3(96, BB), 256>>>(x, par, pos, dep);

    int smem = SPAN_SMEM_FLOATS * 4;
    cudaFuncSetAttribute(span_kernel, cudaFuncAttributeMaxDynamicSharedMemorySize, smem);
    span_kernel<<<dim3(6, NCHUNK, BB), 384, smem>>>(x, out, write_aux);
}